// round 9
// baseline (speedup 1.0000x reference)
#include <cuda_runtime.h>
#include <cstdint>

typedef uint32_t u32;

#define IN_DIM 16
#define HID 32
#define OUT_DIM 8
#define TPB 128
#define TILE_M 128   /* 4 warps x 32 rows (mt=2) */

/* ---- fragment-ordered tf32 weight tables ----
   uint4 = {b0_even, b1_even, b0_odd, b1_odd} for a k-tile pair.
   k-perm: pair u, slot j in 0..3  ->  logical k = 16u + 4*ctg + j
   n-perm (32-col groups): slot (nt4, g) -> n = (nt4>>1)*16 + (nt4&1)*2 + (g>>1)*4 + (g&1) */
__device__ uint4 gB1[768];   /* z|r: 3 pairs x 8 nt x 32 lanes */
__device__ uint4 gBh[384];   /* h~ : 3 pairs x 4 nt x 32 lanes */
__device__ uint4 gBl[64];    /* lin: 2 pairs x 1 nt x 32 lanes */

/* ---------------- helpers ---------------- */
__device__ __forceinline__ u32 tf32c(float f) {
    u32 r;
    asm("cvt.rn.tf32.f32 %0, %1;" : "=r"(r) : "f"(f));
    return r;
}
__device__ __forceinline__ float tanh_hw(float x) {
    float y;
    asm("tanh.approx.f32 %0, %1;" : "=f"(y) : "f"(x));
    return y;
}
__device__ __forceinline__ float sigm(float v) {
    return fmaf(tanh_hw(0.5f * v), 0.5f, 0.5f);
}
__device__ __forceinline__ void ldg4f(float* d, const float* p, bool v) {
    float4 t = make_float4(0.0f, 0.0f, 0.0f, 0.0f);
    if (v) t = *reinterpret_cast<const float4*>(p);
    d[0] = t.x; d[1] = t.y; d[2] = t.z; d[3] = t.w;
}
__device__ __forceinline__ void mma1688(float c[4], const u32 a[4], u32 b0, u32 b1) {
    asm volatile(
        "mma.sync.aligned.m16n8k8.row.col.f32.tf32.tf32.f32 "
        "{%0,%1,%2,%3}, {%4,%5,%6,%7}, {%8,%9}, {%0,%1,%2,%3};"
        : "+f"(c[0]), "+f"(c[1]), "+f"(c[2]), "+f"(c[3])
        : "r"(a[0]), "r"(a[1]), "r"(a[2]), "r"(a[3]), "r"(b0), "r"(b1));
}
__device__ __forceinline__ void mma_pair(float c[4], const u32 ae[4], const u32 ao[4], uint4 B) {
    mma1688(c, ae, B.x, B.y);
    mma1688(c, ao, B.z, B.w);
}
/* rows v0 (gid), v1 (gid+8): 4 contiguous logical k each -> even/odd tile frags */
__device__ __forceinline__ void packA(const float* v0, const float* v1, u32 ae[4], u32 ao[4]) {
    ae[0] = tf32c(v0[0]); ae[1] = tf32c(v1[0]); ae[2] = tf32c(v0[1]); ae[3] = tf32c(v1[1]);
    ao[0] = tf32c(v0[2]); ao[1] = tf32c(v1[2]); ao[2] = tf32c(v0[3]); ao[3] = tf32c(v1[3]);
}

/* ====== prep: fold w0+w1, apply k/n perms, emit tf32 fragments ====== */
__global__ void rgcn_prep(const float* __restrict__ wz, const float* __restrict__ wr,
                          const float* __restrict__ wh, const float* __restrict__ wl) {
    int idx = blockIdx.x * blockDim.x + threadIdx.x;
    if (idx >= 38 * 32) return;
    int lane = idx & 31, fid = idx >> 5;
    int gid = lane >> 2, ctg = lane & 3;

    u32 o[4];
    if (fid < 24) {                 /* B1: z (nt 0..3) | r (nt 4..7) */
        int u = fid >> 3, nt = fid & 7, nt4 = nt & 3;
        int L = ((nt4 >> 1) << 4) + ((nt4 & 1) << 1) + ((gid >> 1) << 2) + (gid & 1);
        #pragma unroll
        for (int j = 0; j < 4; j++) {
            int k = u * 16 + ctg * 4 + j;
            float val = (nt < 4) ? wz[k * 32 + L] + wz[1536 + k * 32 + L]
                                 : wr[k * 32 + L] + wr[1536 + k * 32 + L];
            o[j] = tf32c(val);
        }
        gB1[fid * 32 + lane] = make_uint4(o[0], o[1], o[2], o[3]);
    } else if (fid < 36) {          /* B_h */
        int f = fid - 24;
        int u = f >> 2, nt = f & 3;
        int L = ((nt >> 1) << 4) + ((nt & 1) << 1) + ((gid >> 1) << 2) + (gid & 1);
        #pragma unroll
        for (int j = 0; j < 4; j++) {
            int k = u * 16 + ctg * 4 + j;
            o[j] = tf32c(wh[k * 32 + L] + wh[1536 + k * 32 + L]);
        }
        gBh[f * 32 + lane] = make_uint4(o[0], o[1], o[2], o[3]);
    } else {                        /* B_lin (identity n) */
        int u = fid - 36;
        #pragma unroll
        for (int j = 0; j < 4; j++) {
            int k = u * 16 + ctg * 4 + j;
            o[j] = tf32c(wl[k * 8 + gid]);
        }
        gBl[u * 32 + lane] = make_uint4(o[0], o[1], o[2], o[3]);
    }
}

/* ====== main fused kernel: mt=2, zero smem, tf32, 4 CTAs/SM ====== */
__global__ void __launch_bounds__(TPB, 4) rgcn_mma_kernel(
    const float* __restrict__ x, const float* __restrict__ h,
    const float* __restrict__ bz, const float* __restrict__ br,
    const float* __restrict__ bh, const float* __restrict__ bl,
    float* __restrict__ out, float* __restrict__ hnew, int N)
{
    const int tid  = threadIdx.x;
    const int lane = tid & 31;
    const int warp = tid >> 5;
    const int gid  = lane >> 2, ctg = lane & 3;
    const int c4   = 4 * ctg, c2 = 2 * ctg;
    const int rowBase = blockIdx.x * TILE_M + warp * 32;

    int  rr[2][2];
    bool vv[2][2];
    #pragma unroll
    for (int mt = 0; mt < 2; mt++)
        #pragma unroll
        for (int rh = 0; rh < 2; rh++) {
            rr[mt][rh] = rowBase + mt * 16 + gid + rh * 8;
            vv[mt][rh] = rr[mt][rh] < N;
        }

    /* ---- vectorized loads at permuted fragment coordinates ---- */
    float hA[2][2][4], hB[2][2][4];
    u32 xae[2][4], xao[2][4];
    #pragma unroll
    for (int mt = 0; mt < 2; mt++) {
        float t0[4], t1[4];
        ldg4f(t0, x + (size_t)rr[mt][0] * IN_DIM + c4, vv[mt][0]);
        ldg4f(t1, x + (size_t)rr[mt][1] * IN_DIM + c4, vv[mt][1]);
        packA(t0, t1, xae[mt], xao[mt]);
        #pragma unroll
        for (int rh = 0; rh < 2; rh++) {
            ldg4f(hA[mt][rh], h + (size_t)rr[mt][rh] * HID + c4,      vv[mt][rh]);
            ldg4f(hB[mt][rh], h + (size_t)rr[mt][rh] * HID + 16 + c4, vv[mt][rh]);
        }
    }

    /* ---- GEMM1: C1[32x64] = [x|h] @ B_zr (fused z|r) ---- */
    float c1[2][8][4];
    #pragma unroll
    for (int mt = 0; mt < 2; mt++)
        #pragma unroll
        for (int nt = 0; nt < 8; nt++)
            #pragma unroll
            for (int i = 0; i < 4; i++) c1[mt][nt][i] = 0.0f;

    #pragma unroll
    for (int u = 0; u < 3; u++) {
        u32 ae[2][4], ao[2][4];
        #pragma unroll
        for (int mt = 0; mt < 2; mt++) {
            if (u == 0) {
                #pragma unroll
                for (int j = 0; j < 4; j++) { ae[mt][j] = xae[mt][j]; ao[mt][j] = xao[mt][j]; }
            } else if (u == 1) packA(hA[mt][0], hA[mt][1], ae[mt], ao[mt]);
            else               packA(hB[mt][0], hB[mt][1], ae[mt], ao[mt]);
        }
        #pragma unroll
        for (int nt = 0; nt < 8; nt++) {
            uint4 B = __ldg(&gB1[(u * 8 + nt) * 32 + lane]);
            mma_pair(c1[0][nt], ae[0], ao[0], B);
            mma_pair(c1[1][nt], ae[1], ao[1], B);
        }
    }

    /* ---- epilogue 1: a2 = h * sigmoid(r+br); zg = sigmoid(z+bz) in-place ---- */
    float brA[4], brB[4], bzA[4], bzB[4];
    ldg4f(brA, br + c4, true);
    ldg4f(brB, br + 16 + c4, true);
    ldg4f(bzA, bz + c4, true);
    ldg4f(bzB, bz + 16 + c4, true);

    u32 a2e[2][2][4], a2o[2][2][4];   /* [mt][grp] -> pair u=grp+1 */
    #pragma unroll
    for (int mt = 0; mt < 2; mt++)
        #pragma unroll
        for (int grp = 0; grp < 2; grp++) {
            const float* brv = grp ? brB : brA;
            const float* bzv = grp ? bzB : bzA;
            float vals[2][4];
            #pragma unroll
            for (int rh = 0; rh < 2; rh++) {
                const float* hX = grp ? hB[mt][rh] : hA[mt][rh];
                #pragma unroll
                for (int q = 0; q < 4; q++) {
                    int nt = grp * 2 + (q >> 1);
                    int ri = rh * 2 + (q & 1);
                    vals[rh][q] = hX[q] * sigm(c1[mt][nt + 4][ri] + brv[q]);
                    /* convert z pre-activation to gate in place (frees bz later) */
                    if (rh == 0 || true) { }
                    c1[mt][nt][ri] = sigm(c1[mt][nt][ri] + bzv[q]);
                }
            }
            packA(vals[0], vals[1], a2e[mt][grp], a2o[mt][grp]);
        }
    /* hA/hB are now dead — h_old reloaded from cache in epilogue 2 */

    /* ---- GEMM2: CC[32x32] = [x | a2] @ B_h ---- */
    float cc[2][4][4];
    #pragma unroll
    for (int mt = 0; mt < 2; mt++)
        #pragma unroll
        for (int nt = 0; nt < 4; nt++)
            #pragma unroll
            for (int i = 0; i < 4; i++) cc[mt][nt][i] = 0.0f;

    #pragma unroll
    for (int u = 0; u < 3; u++) {
        #pragma unroll
        for (int nt = 0; nt < 4; nt++) {
            uint4 B = __ldg(&gBh[(u * 4 + nt) * 32 + lane]);
            #pragma unroll
            for (int mt = 0; mt < 2; mt++) {
                const u32* ae = (u == 0) ? xae[mt] : a2e[mt][u - 1];
                const u32* ao = (u == 0) ? xao[mt] : a2o[mt][u - 1];
                mma_pair(cc[mt][nt], ae, ao, B);
            }
        }
    }

    /* ---- epilogue 2: hn = h~ + zg*(h - h~); store; pack relu(hn) ---- */
    float bhA[4], bhB[4];
    ldg4f(bhA, bh + c4, true);
    ldg4f(bhB, bh + 16 + c4, true);

    u32 re[2][2][4], ro[2][2][4];
    #pragma unroll
    for (int mt = 0; mt < 2; mt++)
        #pragma unroll
        for (int grp = 0; grp < 2; grp++) {
            const float* bhv = grp ? bhB : bhA;
            float rel[2][4];
            #pragma unroll
            for (int rh = 0; rh < 2; rh++) {
                float hX[4];   /* reload h_old from cache */
                ldg4f(hX, h + (size_t)rr[mt][rh] * HID + grp * 16 + c4, vv[mt][rh]);
                float hn[4];
                #pragma unroll
                for (int q = 0; q < 4; q++) {
                    int nt = grp * 2 + (q >> 1);
                    int ri = rh * 2 + (q & 1);
                    float zg = c1[mt][nt][ri];
                    float ht = tanh_hw(cc[mt][nt][ri] + bhv[q]);
                    hn[q] = fmaf(zg, hX[q] - ht, ht);
                    rel[rh][q] = fmaxf(hn[q], 0.0f);
                }
                if (vv[mt][rh])
                    *reinterpret_cast<float4*>(hnew + (size_t)rr[mt][rh] * HID + grp * 16 + c4) =
                        make_float4(hn[0], hn[1], hn[2], hn[3]);
            }
            packA(rel[0], rel[1], re[mt][grp], ro[mt][grp]);
        }

    /* ---- GEMM3: out[32x8] = relu(hn) @ w_lin ---- */
    float co[2][4];
    #pragma unroll
    for (int mt = 0; mt < 2; mt++)
        #pragma unroll
        for (int i = 0; i < 4; i++) co[mt][i] = 0.0f;

    #pragma unroll
    for (int u = 0; u < 2; u++) {
        uint4 B = __ldg(&gBl[u * 32 + lane]);
        #pragma unroll
        for (int mt = 0; mt < 2; mt++)
            mma_pair(co[mt], re[mt][u], ro[mt][u], B);
    }

    float2 blv = *reinterpret_cast<const float2*>(bl + c2);
    #pragma unroll
    for (int mt = 0; mt < 2; mt++) {
        if (vv[mt][0])
            *reinterpret_cast<float2*>(out + (size_t)rr[mt][0] * OUT_DIM + c2) =
                make_float2(co[mt][0] + blv.x, co[mt][1] + blv.y);
        if (vv[mt][1])
            *reinterpret_cast<float2*>(out + (size_t)rr[mt][1] * OUT_DIM + c2) =
                make_float2(co[mt][2] + blv.x, co[mt][3] + blv.y);
    }
}

extern "C" void kernel_launch(void* const* d_in, const int* in_sizes, int n_in,
                              void* d_out, int out_size) {
    const float* x  = (const float*)d_in[0];
    const float* h  = (const float*)d_in[3];
    const float* wz = (const float*)d_in[4];
    const float* bz = (const float*)d_in[5];
    const float* wr = (const float*)d_in[6];
    const float* br = (const float*)d_in[7];
    const float* wh = (const float*)d_in[8];
    const float* bh = (const float*)d_in[9];
    const float* wl = (const float*)d_in[10];
    const float* bl = (const float*)d_in[11];

    int N = in_sizes[0] / IN_DIM;
    float* out  = (float*)d_out;
    float* hnew = out + (size_t)N * OUT_DIM;

    rgcn_prep<<<5, 256>>>(wz, wr, wh, wl);

    int grid = (N + TILE_M - 1) / TILE_M;
    rgcn_mma_kernel<<<grid, TPB>>>(x, h, bz, br, bh, bl, out, hnew, N);
}

// round 10
// speedup vs baseline: 1.2755x; 1.2755x over previous
#include <cuda_runtime.h>
#include <cstdint>

typedef uint32_t u32;

#define IN_DIM 16
#define HID 32
#define OUT_DIM 8
#define TPB 128
#define TILE_M 128   /* 4 warps x 32 rows (mt=2) */

/* ---- fragment-ordered tf32 weight tables ----
   uint4 = {b0_even, b1_even, b0_odd, b1_odd} for a k-tile pair.
   k-perm: pair u, slot j in 0..3  ->  logical k = 16u + 4*ctg + j
   n-perm (32-col groups): slot (nt4, g) -> n = (nt4>>1)*16 + (nt4&1)*2 + (g>>1)*4 + (g&1) */
__device__ uint4 gB1[768];   /* z: nt 0..3 | r: nt 4..7, 3 pairs x 32 lanes */
__device__ uint4 gBh[384];   /* h~ : 3 pairs x 4 nt x 32 lanes */
__device__ uint4 gBl[64];    /* lin: 2 pairs x 1 nt x 32 lanes */

/* ---------------- helpers ---------------- */
__device__ __forceinline__ u32 tf32c(float f) {
    u32 r;
    asm("cvt.rn.tf32.f32 %0, %1;" : "=r"(r) : "f"(f));
    return r;
}
__device__ __forceinline__ float tanh_hw(float x) {
    float y;
    asm("tanh.approx.f32 %0, %1;" : "=f"(y) : "f"(x));
    return y;
}
__device__ __forceinline__ float sigm(float v) {
    return fmaf(tanh_hw(0.5f * v), 0.5f, 0.5f);
}
__device__ __forceinline__ void ldg4f(float* d, const float* p, bool v) {
    float4 t = make_float4(0.0f, 0.0f, 0.0f, 0.0f);
    if (v) t = *reinterpret_cast<const float4*>(p);
    d[0] = t.x; d[1] = t.y; d[2] = t.z; d[3] = t.w;
}
__device__ __forceinline__ void mma1688(float c[4], const u32 a[4], u32 b0, u32 b1) {
    asm volatile(
        "mma.sync.aligned.m16n8k8.row.col.f32.tf32.tf32.f32 "
        "{%0,%1,%2,%3}, {%4,%5,%6,%7}, {%8,%9}, {%0,%1,%2,%3};"
        : "+f"(c[0]), "+f"(c[1]), "+f"(c[2]), "+f"(c[3])
        : "r"(a[0]), "r"(a[1]), "r"(a[2]), "r"(a[3]), "r"(b0), "r"(b1));
}
__device__ __forceinline__ void mma_pair(float c[4], const u32 ae[4], const u32 ao[4], uint4 B) {
    mma1688(c, ae, B.x, B.y);
    mma1688(c, ao, B.z, B.w);
}
/* rows v0 (gid), v1 (gid+8): 4 contiguous logical k each -> even/odd tile frags */
__device__ __forceinline__ void packA(const float* v0, const float* v1, u32 ae[4], u32 ao[4]) {
    ae[0] = tf32c(v0[0]); ae[1] = tf32c(v1[0]); ae[2] = tf32c(v0[1]); ae[3] = tf32c(v1[1]);
    ao[0] = tf32c(v0[2]); ao[1] = tf32c(v1[2]); ao[2] = tf32c(v0[3]); ao[3] = tf32c(v1[3]);
}

/* ====== prep: fold w0+w1, apply k/n perms, emit tf32 fragments ====== */
__global__ void rgcn_prep(const float* __restrict__ wz, const float* __restrict__ wr,
                          const float* __restrict__ wh, const float* __restrict__ wl) {
    int idx = blockIdx.x * blockDim.x + threadIdx.x;
    if (idx >= 38 * 32) return;
    int lane = idx & 31, fid = idx >> 5;
    int gid = lane >> 2, ctg = lane & 3;

    u32 o[4];
    if (fid < 24) {                 /* B1: z (nt 0..3) | r (nt 4..7) */
        int u = fid >> 3, nt = fid & 7, nt4 = nt & 3;
        int L = ((nt4 >> 1) << 4) + ((nt4 & 1) << 1) + ((gid >> 1) << 2) + (gid & 1);
        #pragma unroll
        for (int j = 0; j < 4; j++) {
            int k = u * 16 + ctg * 4 + j;
            float val = (nt < 4) ? wz[k * 32 + L] + wz[1536 + k * 32 + L]
                                 : wr[k * 32 + L] + wr[1536 + k * 32 + L];
            o[j] = tf32c(val);
        }
        gB1[fid * 32 + lane] = make_uint4(o[0], o[1], o[2], o[3]);
    } else if (fid < 36) {          /* B_h */
        int f = fid - 24;
        int u = f >> 2, nt = f & 3;
        int L = ((nt >> 1) << 4) + ((nt & 1) << 1) + ((gid >> 1) << 2) + (gid & 1);
        #pragma unroll
        for (int j = 0; j < 4; j++) {
            int k = u * 16 + ctg * 4 + j;
            o[j] = tf32c(wh[k * 32 + L] + wh[1536 + k * 32 + L]);
        }
        gBh[f * 32 + lane] = make_uint4(o[0], o[1], o[2], o[3]);
    } else {                        /* B_lin (identity n) */
        int u = fid - 36;
        #pragma unroll
        for (int j = 0; j < 4; j++) {
            int k = u * 16 + ctg * 4 + j;
            o[j] = tf32c(wl[k * 8 + gid]);
        }
        gBl[u * 32 + lane] = make_uint4(o[0], o[1], o[2], o[3]);
    }
}

/* ====== main: 4 sequential GEMMs, no accumulator set spans two GEMMs ====== */
__global__ void __launch_bounds__(TPB, 4) rgcn_mma_kernel(
    const float* __restrict__ x, const float* __restrict__ h,
    const float* __restrict__ bz, const float* __restrict__ br,
    const float* __restrict__ bh, const float* __restrict__ bl,
    float* __restrict__ out, float* __restrict__ hnew, int N)
{
    const int tid  = threadIdx.x;
    const int lane = tid & 31;
    const int warp = tid >> 5;
    const int gid  = lane >> 2, ctg = lane & 3;
    const int c4   = 4 * ctg, c2 = 2 * ctg;
    const int rowBase = blockIdx.x * TILE_M + warp * 32;

    int  rr[2][2];
    bool vv[2][2];
    #pragma unroll
    for (int mt = 0; mt < 2; mt++)
        #pragma unroll
        for (int rh = 0; rh < 2; rh++) {
            rr[mt][rh] = rowBase + mt * 16 + gid + rh * 8;
            vv[mt][rh] = rr[mt][rh] < N;
        }

    /* ---- loads at permuted fragment coordinates ---- */
    float hA[2][2][4], hB[2][2][4];
    u32 xae[2][4], xao[2][4];
    #pragma unroll
    for (int mt = 0; mt < 2; mt++) {
        float t0[4], t1[4];
        ldg4f(t0, x + (size_t)rr[mt][0] * IN_DIM + c4, vv[mt][0]);
        ldg4f(t1, x + (size_t)rr[mt][1] * IN_DIM + c4, vv[mt][1]);
        packA(t0, t1, xae[mt], xao[mt]);
        #pragma unroll
        for (int rh = 0; rh < 2; rh++) {
            ldg4f(hA[mt][rh], h + (size_t)rr[mt][rh] * HID + c4,      vv[mt][rh]);
            ldg4f(hB[mt][rh], h + (size_t)rr[mt][rh] * HID + 16 + c4, vv[mt][rh]);
        }
    }

    /* ---- GEMM_r: cr[32x32] = [x|h] @ B_r (gB1 nt 4..7) ---- */
    float cr[2][4][4];
    #pragma unroll
    for (int mt = 0; mt < 2; mt++)
        #pragma unroll
        for (int nt = 0; nt < 4; nt++)
            #pragma unroll
            for (int i = 0; i < 4; i++) cr[mt][nt][i] = 0.0f;

    #pragma unroll
    for (int u = 0; u < 3; u++) {
        u32 ae[2][4], ao[2][4];
        #pragma unroll
        for (int mt = 0; mt < 2; mt++) {
            if (u == 0) {
                #pragma unroll
                for (int j = 0; j < 4; j++) { ae[mt][j] = xae[mt][j]; ao[mt][j] = xao[mt][j]; }
            } else if (u == 1) packA(hA[mt][0], hA[mt][1], ae[mt], ao[mt]);
            else               packA(hB[mt][0], hB[mt][1], ae[mt], ao[mt]);
        }
        #pragma unroll
        for (int nt = 0; nt < 4; nt++) {
            uint4 B = __ldg(&gB1[(u * 8 + 4 + nt) * 32 + lane]);
            mma_pair(cr[0][nt], ae[0], ao[0], B);
            mma_pair(cr[1][nt], ae[1], ao[1], B);
        }
    }

    /* ---- epilogue 1: a2 = h * sigmoid(r+br); pack into A-frags; cr dies ---- */
    u32 a2e[2][2][4], a2o[2][2][4];   /* [mt][grp] -> pair u=grp+1 */
    {
        float brA[4], brB[4];
        ldg4f(brA, br + c4, true);
        ldg4f(brB, br + 16 + c4, true);
        #pragma unroll
        for (int mt = 0; mt < 2; mt++)
            #pragma unroll
            for (int grp = 0; grp < 2; grp++) {
                const float* brv = grp ? brB : brA;
                float vals[2][4];
                #pragma unroll
                for (int rh = 0; rh < 2; rh++) {
                    const float* hX = grp ? hB[mt][rh] : hA[mt][rh];
                    #pragma unroll
                    for (int q = 0; q < 4; q++) {
                        int nt = grp * 2 + (q >> 1);
                        int ri = rh * 2 + (q & 1);
                        vals[rh][q] = hX[q] * sigm(cr[mt][nt][ri] + brv[q]);
                    }
                }
                packA(vals[0], vals[1], a2e[mt][grp], a2o[mt][grp]);
            }
    }

    /* ---- GEMM_h: cc[32x32] = [x | a2] @ B_h ---- */
    float cc[2][4][4];
    #pragma unroll
    for (int mt = 0; mt < 2; mt++)
        #pragma unroll
        for (int nt = 0; nt < 4; nt++)
            #pragma unroll
            for (int i = 0; i < 4; i++) cc[mt][nt][i] = 0.0f;

    #pragma unroll
    for (int u = 0; u < 3; u++) {
        #pragma unroll
        for (int nt = 0; nt < 4; nt++) {
            uint4 B = __ldg(&gBh[(u * 4 + nt) * 32 + lane]);
            #pragma unroll
            for (int mt = 0; mt < 2; mt++) {
                const u32* ae = (u == 0) ? xae[mt] : a2e[mt][u - 1];
                const u32* ao = (u == 0) ? xao[mt] : a2o[mt][u - 1];
                mma_pair(cc[mt][nt], ae, ao, B);
            }
        }
    }

    /* ---- ht = tanh(cc + bh) in place; a2 dies ---- */
    {
        float bhA[4], bhB[4];
        ldg4f(bhA, bh + c4, true);
        ldg4f(bhB, bh + 16 + c4, true);
        #pragma unroll
        for (int mt = 0; mt < 2; mt++)
            #pragma unroll
            for (int nt = 0; nt < 4; nt++) {
                const float* bhv = (nt >> 1) ? bhB : bhA;
                #pragma unroll
                for (int i = 0; i < 4; i++) {
                    int q = ((nt & 1) << 1) + (i >> 1);
                    cc[mt][nt][i] = tanh_hw(cc[mt][nt][i] + bhv[q]);
                }
            }
    }

    /* ---- GEMM_z: cz[32x32] = [x|h] @ B_z (gB1 nt 0..3) ---- */
    float cz[2][4][4];
    #pragma unroll
    for (int mt = 0; mt < 2; mt++)
        #pragma unroll
        for (int nt = 0; nt < 4; nt++)
            #pragma unroll
            for (int i = 0; i < 4; i++) cz[mt][nt][i] = 0.0f;

    #pragma unroll
    for (int u = 0; u < 3; u++) {
        u32 ae[2][4], ao[2][4];
        #pragma unroll
        for (int mt = 0; mt < 2; mt++) {
            if (u == 0) {
                #pragma unroll
                for (int j = 0; j < 4; j++) { ae[mt][j] = xae[mt][j]; ao[mt][j] = xao[mt][j]; }
            } else if (u == 1) packA(hA[mt][0], hA[mt][1], ae[mt], ao[mt]);
            else               packA(hB[mt][0], hB[mt][1], ae[mt], ao[mt]);
        }
        #pragma unroll
        for (int nt = 0; nt < 4; nt++) {
            uint4 B = __ldg(&gB1[(u * 8 + nt) * 32 + lane]);
            mma_pair(cz[0][nt], ae[0], ao[0], B);
            mma_pair(cz[1][nt], ae[1], ao[1], B);
        }
    }

    /* ---- combine: hn = ht + zg*(h - ht); store; pack relu(hn) ---- */
    u32 re[2][2][4], ro[2][2][4];
    {
        float bzA[4], bzB[4];
        ldg4f(bzA, bz + c4, true);
        ldg4f(bzB, bz + 16 + c4, true);
        #pragma unroll
        for (int mt = 0; mt < 2; mt++)
            #pragma unroll
            for (int grp = 0; grp < 2; grp++) {
                const float* bzv = grp ? bzB : bzA;
                float rel[2][4];
                #pragma unroll
                for (int rh = 0; rh < 2; rh++) {
                    const float* hX = grp ? hB[mt][rh] : hA[mt][rh];
                    float hn[4];
                    #pragma unroll
                    for (int q = 0; q < 4; q++) {
                        int nt = grp * 2 + (q >> 1);
                        int ri = rh * 2 + (q & 1);
                        float zg = sigm(cz[mt][nt][ri] + bzv[q]);
                        float ht = cc[mt][nt][ri];
                        hn[q] = fmaf(zg, hX[q] - ht, ht);
                        rel[rh][q] = fmaxf(hn[q], 0.0f);
                    }
                    if (vv[mt][rh])
                        *reinterpret_cast<float4*>(hnew + (size_t)rr[mt][rh] * HID + grp * 16 + c4) =
                            make_float4(hn[0], hn[1], hn[2], hn[3]);
                }
                packA(rel[0], rel[1], re[mt][grp], ro[mt][grp]);
            }
    }

    /* ---- GEMM3: out[32x8] = relu(hn) @ w_lin ---- */
    float co[2][4];
    #pragma unroll
    for (int mt = 0; mt < 2; mt++)
        #pragma unroll
        for (int i = 0; i < 4; i++) co[mt][i] = 0.0f;

    #pragma unroll
    for (int u = 0; u < 2; u++) {
        uint4 B = __ldg(&gBl[u * 32 + lane]);
        #pragma unroll
        for (int mt = 0; mt < 2; mt++)
            mma_pair(co[mt], re[mt][u], ro[mt][u], B);
    }

    float2 blv = *reinterpret_cast<const float2*>(bl + c2);
    #pragma unroll
    for (int mt = 0; mt < 2; mt++) {
        if (vv[mt][0])
            *reinterpret_cast<float2*>(out + (size_t)rr[mt][0] * OUT_DIM + c2) =
                make_float2(co[mt][0] + blv.x, co[mt][1] + blv.y);
        if (vv[mt][1])
            *reinterpret_cast<float2*>(out + (size_t)rr[mt][1] * OUT_DIM + c2) =
                make_float2(co[mt][2] + blv.x, co[mt][3] + blv.y);
    }
}

extern "C" void kernel_launch(void* const* d_in, const int* in_sizes, int n_in,
                              void* d_out, int out_size) {
    const float* x  = (const float*)d_in[0];
    const float* h  = (const float*)d_in[3];
    const float* wz = (const float*)d_in[4];
    const float* bz = (const float*)d_in[5];
    const float* wr = (const float*)d_in[6];
    const float* br = (const float*)d_in[7];
    const float* wh = (const float*)d_in[8];
    const float* bh = (const float*)d_in[9];
    const float* wl = (const float*)d_in[10];
    const float* bl = (const float*)d_in[11];

    int N = in_sizes[0] / IN_DIM;
    float* out  = (float*)d_out;
    float* hnew = out + (size_t)N * OUT_DIM;

    rgcn_prep<<<5, 256>>>(wz, wr, wh, wl);

    int grid = (N + TILE_M - 1) / TILE_M;
    rgcn_mma_kernel<<<grid, TPB>>>(x, h, bz, br, bh, bl, out, hnew, N);
}

// round 11
// speedup vs baseline: 1.3966x; 1.0950x over previous
#include <cuda_runtime.h>
#include <cstdint>

typedef uint32_t u32;

#define IN_DIM 16
#define HID 32
#define OUT_DIM 8
#define TPB 128
#define TILE_M 128   /* 4 warps x 32 rows (mt=2) */

/* ---- fragment-ordered tf32 weight tables ----
   uint4 = {b0_even, b1_even, b0_odd, b1_odd} for a k-tile pair.
   k-perm: pair u, slot j in 0..3  ->  logical k = 16u + 4*ctg + j
   n-perm (32-col groups): slot (nt4, g) -> n = (nt4>>1)*16 + (nt4&1)*2 + (g>>1)*4 + (g&1) */
__device__ uint4 gB1[768];   /* z: nt 0..3 | r: nt 4..7, 3 pairs x 32 lanes */
__device__ uint4 gBh[384];   /* h~ : 3 pairs x 4 nt x 32 lanes */
__device__ uint4 gBl[64];    /* lin: 2 pairs x 1 nt x 32 lanes */

/* ---------------- helpers ---------------- */
__device__ __forceinline__ u32 tf32c(float f) {
    u32 r;
    asm("cvt.rn.tf32.f32 %0, %1;" : "=r"(r) : "f"(f));
    return r;
}
__device__ __forceinline__ float tanh_hw(float x) {
    float y;
    asm("tanh.approx.f32 %0, %1;" : "=f"(y) : "f"(x));
    return y;
}
__device__ __forceinline__ float sigm(float v) {
    return fmaf(tanh_hw(0.5f * v), 0.5f, 0.5f);
}
__device__ __forceinline__ void ldg4f(float* d, const float* p, bool v) {
    float4 t = make_float4(0.0f, 0.0f, 0.0f, 0.0f);
    if (v) t = *reinterpret_cast<const float4*>(p);
    d[0] = t.x; d[1] = t.y; d[2] = t.z; d[3] = t.w;
}
__device__ __forceinline__ void mma1688(float c[4], const u32 a[4], u32 b0, u32 b1) {
    asm volatile(
        "mma.sync.aligned.m16n8k8.row.col.f32.tf32.tf32.f32 "
        "{%0,%1,%2,%3}, {%4,%5,%6,%7}, {%8,%9}, {%0,%1,%2,%3};"
        : "+f"(c[0]), "+f"(c[1]), "+f"(c[2]), "+f"(c[3])
        : "r"(a[0]), "r"(a[1]), "r"(a[2]), "r"(a[3]), "r"(b0), "r"(b1));
}
__device__ __forceinline__ void mma_pair(float c[4], const u32 ae[4], const u32 ao[4], uint4 B) {
    mma1688(c, ae, B.x, B.y);
    mma1688(c, ao, B.z, B.w);
}
/* rows v0 (gid), v1 (gid+8): 4 contiguous logical k each -> even/odd tile frags */
__device__ __forceinline__ void packA(const float* v0, const float* v1, u32 ae[4], u32 ao[4]) {
    ae[0] = tf32c(v0[0]); ae[1] = tf32c(v1[0]); ae[2] = tf32c(v0[1]); ae[3] = tf32c(v1[1]);
    ao[0] = tf32c(v0[2]); ao[1] = tf32c(v1[2]); ao[2] = tf32c(v0[3]); ao[3] = tf32c(v1[3]);
}

/* ====== prep: fold w0+w1, apply k/n perms, emit tf32 fragments ====== */
__global__ void rgcn_prep(const float* __restrict__ wz, const float* __restrict__ wr,
                          const float* __restrict__ wh, const float* __restrict__ wl) {
    int idx = blockIdx.x * blockDim.x + threadIdx.x;
    if (idx >= 38 * 32) return;
    int lane = idx & 31, fid = idx >> 5;
    int gid = lane >> 2, ctg = lane & 3;

    u32 o[4];
    if (fid < 24) {                 /* B1: z (nt 0..3) | r (nt 4..7) */
        int u = fid >> 3, nt = fid & 7, nt4 = nt & 3;
        int L = ((nt4 >> 1) << 4) + ((nt4 & 1) << 1) + ((gid >> 1) << 2) + (gid & 1);
        #pragma unroll
        for (int j = 0; j < 4; j++) {
            int k = u * 16 + ctg * 4 + j;
            float val = (nt < 4) ? wz[k * 32 + L] + wz[1536 + k * 32 + L]
                                 : wr[k * 32 + L] + wr[1536 + k * 32 + L];
            o[j] = tf32c(val);
        }
        gB1[fid * 32 + lane] = make_uint4(o[0], o[1], o[2], o[3]);
    } else if (fid < 36) {          /* B_h */
        int f = fid - 24;
        int u = f >> 2, nt = f & 3;
        int L = ((nt >> 1) << 4) + ((nt & 1) << 1) + ((gid >> 1) << 2) + (gid & 1);
        #pragma unroll
        for (int j = 0; j < 4; j++) {
            int k = u * 16 + ctg * 4 + j;
            o[j] = tf32c(wh[k * 32 + L] + wh[1536 + k * 32 + L]);
        }
        gBh[f * 32 + lane] = make_uint4(o[0], o[1], o[2], o[3]);
    } else {                        /* B_lin (identity n) */
        int u = fid - 36;
        #pragma unroll
        for (int j = 0; j < 4; j++) {
            int k = u * 16 + ctg * 4 + j;
            o[j] = tf32c(wl[k * 8 + gid]);
        }
        gBl[u * 32 + lane] = make_uint4(o[0], o[1], o[2], o[3]);
    }
}

/* ====== main: gate-split GEMMs, h never persistent (reloaded from L1) ====== */
__global__ void __launch_bounds__(TPB, 4) rgcn_mma_kernel(
    const float* __restrict__ x, const float* __restrict__ h,
    const float* __restrict__ bz, const float* __restrict__ br,
    const float* __restrict__ bh, const float* __restrict__ bl,
    float* __restrict__ out, float* __restrict__ hnew, int N)
{
    const int tid  = threadIdx.x;
    const int lane = tid & 31;
    const int warp = tid >> 5;
    const int gid  = lane >> 2, ctg = lane & 3;
    const int c4   = 4 * ctg, c2 = 2 * ctg;
    const int rowBase = blockIdx.x * TILE_M + warp * 32;

    int  rr[2][2];
    bool vv[2][2];
    #pragma unroll
    for (int mt = 0; mt < 2; mt++)
        #pragma unroll
        for (int rh = 0; rh < 2; rh++) {
            rr[mt][rh] = rowBase + mt * 16 + gid + rh * 8;
            vv[mt][rh] = rr[mt][rh] < N;
        }

    /* ---- x loaded once, kept only as tf32 fragments ---- */
    u32 xae[2][4], xao[2][4];
    #pragma unroll
    for (int mt = 0; mt < 2; mt++) {
        float t0[4], t1[4];
        ldg4f(t0, x + (size_t)rr[mt][0] * IN_DIM + c4, vv[mt][0]);
        ldg4f(t1, x + (size_t)rr[mt][1] * IN_DIM + c4, vv[mt][1]);
        packA(t0, t1, xae[mt], xao[mt]);
    }

    /* ======== phase R: cr = [x|h] @ B_r ; epilogue 1 -> a2 ; h dies ======== */
    u32 a2e[2][2][4], a2o[2][2][4];   /* [mt][grp] -> pair u=grp+1 */
    {
        float hA[2][2][4], hB[2][2][4];
        #pragma unroll
        for (int mt = 0; mt < 2; mt++)
            #pragma unroll
            for (int rh = 0; rh < 2; rh++) {
                ldg4f(hA[mt][rh], h + (size_t)rr[mt][rh] * HID + c4,      vv[mt][rh]);
                ldg4f(hB[mt][rh], h + (size_t)rr[mt][rh] * HID + 16 + c4, vv[mt][rh]);
            }

        float cr[2][4][4];
        #pragma unroll
        for (int mt = 0; mt < 2; mt++)
            #pragma unroll
            for (int nt = 0; nt < 4; nt++)
                #pragma unroll
                for (int i = 0; i < 4; i++) cr[mt][nt][i] = 0.0f;

        #pragma unroll
        for (int u = 0; u < 3; u++) {
            u32 ae[2][4], ao[2][4];
            #pragma unroll
            for (int mt = 0; mt < 2; mt++) {
                if (u == 0) {
                    #pragma unroll
                    for (int j = 0; j < 4; j++) { ae[mt][j] = xae[mt][j]; ao[mt][j] = xao[mt][j]; }
                } else if (u == 1) packA(hA[mt][0], hA[mt][1], ae[mt], ao[mt]);
                else               packA(hB[mt][0], hB[mt][1], ae[mt], ao[mt]);
            }
            #pragma unroll
            for (int nt = 0; nt < 4; nt++) {
                uint4 B = __ldg(&gB1[(u * 8 + 4 + nt) * 32 + lane]);
                mma_pair(cr[0][nt], ae[0], ao[0], B);
                mma_pair(cr[1][nt], ae[1], ao[1], B);
            }
        }

        float brA[4], brB[4];
        ldg4f(brA, br + c4, true);
        ldg4f(brB, br + 16 + c4, true);
        #pragma unroll
        for (int mt = 0; mt < 2; mt++)
            #pragma unroll
            for (int grp = 0; grp < 2; grp++) {
                const float* brv = grp ? brB : brA;
                float vals[2][4];
                #pragma unroll
                for (int rh = 0; rh < 2; rh++) {
                    const float* hX = grp ? hB[mt][rh] : hA[mt][rh];
                    #pragma unroll
                    for (int q = 0; q < 4; q++) {
                        int nt = grp * 2 + (q >> 1);
                        int ri = rh * 2 + (q & 1);
                        vals[rh][q] = hX[q] * sigm(cr[mt][nt][ri] + brv[q]);
                    }
                }
                packA(vals[0], vals[1], a2e[mt][grp], a2o[mt][grp]);
            }
    }   /* hA/hB, cr dead */

    /* ======== phase H: cc = [x | a2] @ B_h ; ht = tanh in place ======== */
    float cc[2][4][4];
    #pragma unroll
    for (int mt = 0; mt < 2; mt++)
        #pragma unroll
        for (int nt = 0; nt < 4; nt++)
            #pragma unroll
            for (int i = 0; i < 4; i++) cc[mt][nt][i] = 0.0f;

    #pragma unroll
    for (int u = 0; u < 3; u++) {
        #pragma unroll
        for (int nt = 0; nt < 4; nt++) {
            uint4 B = __ldg(&gBh[(u * 4 + nt) * 32 + lane]);
            #pragma unroll
            for (int mt = 0; mt < 2; mt++) {
                const u32* ae = (u == 0) ? xae[mt] : a2e[mt][u - 1];
                const u32* ao = (u == 0) ? xao[mt] : a2o[mt][u - 1];
                mma_pair(cc[mt][nt], ae, ao, B);
            }
        }
    }

    {
        float bhA[4], bhB[4];
        ldg4f(bhA, bh + c4, true);
        ldg4f(bhB, bh + 16 + c4, true);
        #pragma unroll
        for (int mt = 0; mt < 2; mt++)
            #pragma unroll
            for (int nt = 0; nt < 4; nt++) {
                const float* bhv = (nt >> 1) ? bhB : bhA;
                #pragma unroll
                for (int i = 0; i < 4; i++) {
                    int q = ((nt & 1) << 1) + (i >> 1);
                    cc[mt][nt][i] = tanh_hw(cc[mt][nt][i] + bhv[q]);
                }
            }
    }   /* a2 dead */

    /* ======== phase Z: cz = [x|h] @ B_z (h reloaded from L1, transient) ==== */
    float cz[2][4][4];
    #pragma unroll
    for (int mt = 0; mt < 2; mt++)
        #pragma unroll
        for (int nt = 0; nt < 4; nt++)
            #pragma unroll
            for (int i = 0; i < 4; i++) cz[mt][nt][i] = 0.0f;

    #pragma unroll
    for (int u = 0; u < 3; u++) {
        u32 ae[2][4], ao[2][4];
        #pragma unroll
        for (int mt = 0; mt < 2; mt++) {
            if (u == 0) {
                #pragma unroll
                for (int j = 0; j < 4; j++) { ae[mt][j] = xae[mt][j]; ao[mt][j] = xao[mt][j]; }
            } else {
                float t0[4], t1[4];   /* L1-hit reload, packed, then dead */
                ldg4f(t0, h + (size_t)rr[mt][0] * HID + (u - 1) * 16 + c4, vv[mt][0]);
                ldg4f(t1, h + (size_t)rr[mt][1] * HID + (u - 1) * 16 + c4, vv[mt][1]);
                packA(t0, t1, ae[mt], ao[mt]);
            }
        }
        #pragma unroll
        for (int nt = 0; nt < 4; nt++) {
            uint4 B = __ldg(&gB1[(u * 8 + nt) * 32 + lane]);
            mma_pair(cz[0][nt], ae[0], ao[0], B);
            mma_pair(cz[1][nt], ae[1], ao[1], B);
        }
    }

    /* ==== epilogue 2: hn = ht + zg*(h - ht); store; pack relu(hn) ==== */
    u32 re[2][2][4], ro[2][2][4];
    {
        float bzA[4], bzB[4];
        ldg4f(bzA, bz + c4, true);
        ldg4f(bzB, bz + 16 + c4, true);
        #pragma unroll
        for (int mt = 0; mt < 2; mt++)
            #pragma unroll
            for (int grp = 0; grp < 2; grp++) {
                const float* bzv = grp ? bzB : bzA;
                float rel[2][4];
                #pragma unroll
                for (int rh = 0; rh < 2; rh++) {
                    float hX[4];   /* L1-hit reload */
                    ldg4f(hX, h + (size_t)rr[mt][rh] * HID + grp * 16 + c4, vv[mt][rh]);
                    float hn[4];
                    #pragma unroll
                    for (int q = 0; q < 4; q++) {
                        int nt = grp * 2 + (q >> 1);
                        int ri = rh * 2 + (q & 1);
                        float zg = sigm(cz[mt][nt][ri] + bzv[q]);
                        float ht = cc[mt][nt][ri];
                        hn[q] = fmaf(zg, hX[q] - ht, ht);
                        rel[rh][q] = fmaxf(hn[q], 0.0f);
                    }
                    if (vv[mt][rh])
                        *reinterpret_cast<float4*>(hnew + (size_t)rr[mt][rh] * HID + grp * 16 + c4) =
                            make_float4(hn[0], hn[1], hn[2], hn[3]);
                }
                packA(rel[0], rel[1], re[mt][grp], ro[mt][grp]);
            }
    }

    /* ---- GEMM3: out[32x8] = relu(hn) @ w_lin ---- */
    float co[2][4];
    #pragma unroll
    for (int mt = 0; mt < 2; mt++)
        #pragma unroll
        for (int i = 0; i < 4; i++) co[mt][i] = 0.0f;

    #pragma unroll
    for (int u = 0; u < 2; u++) {
        uint4 B = __ldg(&gBl[u * 32 + lane]);
        #pragma unroll
        for (int mt = 0; mt < 2; mt++)
            mma_pair(co[mt], re[mt][u], ro[mt][u], B);
    }

    float2 blv = *reinterpret_cast<const float2*>(bl + c2);
    #pragma unroll
    for (int mt = 0; mt < 2; mt++) {
        if (vv[mt][0])
            *reinterpret_cast<float2*>(out + (size_t)rr[mt][0] * OUT_DIM + c2) =
                make_float2(co[mt][0] + blv.x, co[mt][1] + blv.y);
        if (vv[mt][1])
            *reinterpret_cast<float2*>(out + (size_t)rr[mt][1] * OUT_DIM + c2) =
                make_float2(co[mt][2] + blv.x, co[mt][3] + blv.y);
    }
}

extern "C" void kernel_launch(void* const* d_in, const int* in_sizes, int n_in,
                              void* d_out, int out_size) {
    const float* x  = (const float*)d_in[0];
    const float* h  = (const float*)d_in[3];
    const float* wz = (const float*)d_in[4];
    const float* bz = (const float*)d_in[5];
    const float* wr = (const float*)d_in[6];
    const float* br = (const float*)d_in[7];
    const float* wh = (const float*)d_in[8];
    const float* bh = (const float*)d_in[9];
    const float* wl = (const float*)d_in[10];
    const float* bl = (const float*)d_in[11];

    int N = in_sizes[0] / IN_DIM;
    float* out  = (float*)d_out;
    float* hnew = out + (size_t)N * OUT_DIM;

    rgcn_prep<<<5, 256>>>(wz, wr, wh, wl);

    int grid = (N + TILE_M - 1) / TILE_M;
    rgcn_mma_kernel<<<grid, TPB>>>(x, h, bz, br, bh, bl, out, hnew, N);
}